// round 5
// baseline (speedup 1.0000x reference)
#include <cuda_runtime.h>
#include <cuda_bf16.h>
#include <math.h>
#include <stdint.h>

// Problem constants
#define B_SZ    512
#define DFEAT   2048
#define DATTR   312
#define DATTR_P 320              // N padded to 5*64

// mma.sync GEMM tiling: D[512,320] = X[512,2048] @ W^T[320,2048]^T, bf16x3 split
#define MT_BLK  128              // M per CTA
#define NT_BLK  64               // N per CTA
#define BKT     32               // K per smem tile
#define KSLICE  1024             // K per CTA (split-K)
#define NSLICES 6                // 3 terms * 2048 / 1024

// Scratch (__device__ globals: allocation-free, zero-initialized at load)
__device__ __nv_bfloat16 g_Xhi[B_SZ * DFEAT];
__device__ __nv_bfloat16 g_Xlo[B_SZ * DFEAT];
__device__ __nv_bfloat16 g_WhiT[DATTR_P * DFEAT];   // W^T, K-major, rows >=312 stay zero
__device__ __nv_bfloat16 g_WloT[DATTR_P * DFEAT];
__device__ float g_partial[NSLICES][B_SZ][DATTR_P];
__device__ float g_Sf[B_SZ];

// ---------------------------------------------------------------------------
// Kernel 0a: split X into bf16 hi/lo (1 float4 per thread)
// ---------------------------------------------------------------------------
__global__ __launch_bounds__(256) void split_x_kernel(const float* __restrict__ X)
{
    const int i = blockIdx.x * 256 + threadIdx.x;   // over 262144 float4s
    const float4 v = ((const float4*)X)[i];

    __nv_bfloat16 h0 = __float2bfloat16_rn(v.x), h1 = __float2bfloat16_rn(v.y);
    __nv_bfloat16 h2 = __float2bfloat16_rn(v.z), h3 = __float2bfloat16_rn(v.w);
    __nv_bfloat16 l0 = __float2bfloat16_rn(v.x - __bfloat162float(h0));
    __nv_bfloat16 l1 = __float2bfloat16_rn(v.y - __bfloat162float(h1));
    __nv_bfloat16 l2 = __float2bfloat16_rn(v.z - __bfloat162float(h2));
    __nv_bfloat16 l3 = __float2bfloat16_rn(v.w - __bfloat162float(h3));

    ((__nv_bfloat162*)g_Xhi)[2 * i]     = __nv_bfloat162(h0, h1);
    ((__nv_bfloat162*)g_Xhi)[2 * i + 1] = __nv_bfloat162(h2, h3);
    ((__nv_bfloat162*)g_Xlo)[2 * i]     = __nv_bfloat162(l0, l1);
    ((__nv_bfloat162*)g_Xlo)[2 * i + 1] = __nv_bfloat162(l2, l3);
}

// ---------------------------------------------------------------------------
// Kernel 0b: transpose W [2048,312] -> W^T [320,2048] with bf16 hi/lo split
// ---------------------------------------------------------------------------
__global__ void split_w_kernel(const float* __restrict__ Wm)
{
    __shared__ float t[32][33];
    const int n0 = blockIdx.x * 32, k0 = blockIdx.y * 32;
    const int tx = threadIdx.x, ty = threadIdx.y;   // 32 x 8

    #pragma unroll
    for (int r = 0; r < 32; r += 8) {
        const int n = n0 + tx, k = k0 + ty + r;
        t[ty + r][tx] = (n < DATTR) ? Wm[(size_t)k * DATTR + n] : 0.f;
    }
    __syncthreads();
    #pragma unroll
    for (int r = 0; r < 32; r += 8) {
        const int n = n0 + ty + r, k = k0 + tx;
        if (n < DATTR) {
            const float v = t[tx][ty + r];
            const __nv_bfloat16 h = __float2bfloat16_rn(v);
            const __nv_bfloat16 l = __float2bfloat16_rn(v - __bfloat162float(h));
            g_WhiT[(size_t)n * DFEAT + k] = h;
            g_WloT[(size_t)n * DFEAT + k] = l;
        }
    }
}

// ---------------------------------------------------------------------------
// Kernel 1: bf16 mma.sync m16n8k16 GEMM, split-K partials.
// grid (5 n-tiles, 4 m-tiles, 6 k-slices) = 120 CTAs, 256 threads (8 warps).
// Warp grid 4(m) x 2(n); warp tile 32x32 = 2x4 mma atoms; fp32 accum.
// ---------------------------------------------------------------------------
__global__ __launch_bounds__(256) void mma_gemm_kernel()
{
    // stride 40 bf16 (=80B=20 words): fragment 4B loads are bank-conflict-free
    __shared__ __nv_bfloat16 sA[MT_BLK][40];
    __shared__ __nv_bfloat16 sB[NT_BLK][40];

    const int tid   = threadIdx.x;
    const int wid   = tid >> 5;
    const int lane  = tid & 31;
    const int warpM = wid >> 1;          // 0..3
    const int warpN = wid & 1;           // 0..1
    const int nt = blockIdx.x, mt = blockIdx.y, zs = blockIdx.z;

    // term 0: Xhi@Whi   term 1: Xhi@Wlo   term 2: Xlo@Whi
    const int term = zs >> 1;
    const int k0b  = (zs & 1) * KSLICE;
    const int mBase = mt * MT_BLK;
    const int nBase = nt * NT_BLK;
    const __nv_bfloat16* Asrc = ((term < 2) ? g_Xhi : g_Xlo) + (size_t)mBase * DFEAT;
    const __nv_bfloat16* Bsrc = ((term == 1) ? g_WloT : g_WhiT) + (size_t)nBase * DFEAT;

    const int lq = lane >> 2;   // 0..7  (quad row)
    const int lr = lane & 3;    // 0..3

    float acc[2][4][4] = {};

    for (int kt = 0; kt < KSLICE; kt += BKT) {
        const int k = k0b + kt;

        // A tile: 128 rows x 32 k (64B) -> 512 uint4, 2 per thread
        #pragma unroll
        for (int it = 0; it < 2; it++) {
            const int idx = tid + 256 * it;
            const int row = idx >> 2, c = idx & 3;
            *(uint4*)&sA[row][c * 8] = *(const uint4*)(Asrc + (size_t)row * DFEAT + k + c * 8);
        }
        // B tile: 64 rows x 32 k -> 256 uint4, 1 per thread
        {
            const int row = tid >> 2, c = tid & 3;
            *(uint4*)&sB[row][c * 8] = *(const uint4*)(Bsrc + (size_t)row * DFEAT + k + c * 8);
        }
        __syncthreads();

        #pragma unroll
        for (int kk = 0; kk < BKT; kk += 16) {
            // A fragments: 2 m-atoms
            uint32_t a[2][4];
            #pragma unroll
            for (int am = 0; am < 2; am++) {
                const int r = warpM * 32 + am * 16 + lq;
                a[am][0] = *(const uint32_t*)&sA[r    ][kk + lr * 2    ];
                a[am][1] = *(const uint32_t*)&sA[r + 8][kk + lr * 2    ];
                a[am][2] = *(const uint32_t*)&sA[r    ][kk + lr * 2 + 8];
                a[am][3] = *(const uint32_t*)&sA[r + 8][kk + lr * 2 + 8];
            }
            // B fragments: 4 n-atoms
            uint32_t b[4][2];
            #pragma unroll
            for (int bn = 0; bn < 4; bn++) {
                const int n = warpN * 32 + bn * 8 + lq;
                b[bn][0] = *(const uint32_t*)&sB[n][kk + lr * 2    ];
                b[bn][1] = *(const uint32_t*)&sB[n][kk + lr * 2 + 8];
            }
            #pragma unroll
            for (int am = 0; am < 2; am++) {
                #pragma unroll
                for (int bn = 0; bn < 4; bn++) {
                    asm volatile(
                        "mma.sync.aligned.m16n8k16.row.col.f32.bf16.bf16.f32 "
                        "{%0,%1,%2,%3}, {%4,%5,%6,%7}, {%8,%9}, {%0,%1,%2,%3};"
                        : "+f"(acc[am][bn][0]), "+f"(acc[am][bn][1]),
                          "+f"(acc[am][bn][2]), "+f"(acc[am][bn][3])
                        : "r"(a[am][0]), "r"(a[am][1]), "r"(a[am][2]), "r"(a[am][3]),
                          "r"(b[bn][0]), "r"(b[bn][1]));
                }
            }
        }
        __syncthreads();
    }

    // Epilogue: write fp32 partials
    #pragma unroll
    for (int am = 0; am < 2; am++) {
        const int row0 = mBase + warpM * 32 + am * 16 + lq;
        #pragma unroll
        for (int bn = 0; bn < 4; bn++) {
            const int col = nBase + warpN * 32 + bn * 8 + lr * 2;
            *(float2*)&g_partial[zs][row0    ][col] = make_float2(acc[am][bn][0], acc[am][bn][1]);
            *(float2*)&g_partial[zs][row0 + 8][col] = make_float2(acc[am][bn][2], acc[am][bn][3]);
        }
    }
}

// ---------------------------------------------------------------------------
// Kernel 2: per-row S[i] = rowsum(pre_i) - DATTR * logsumexp(pre_i)  (fp32)
// ---------------------------------------------------------------------------
__global__ __launch_bounds__(128) void rowstats_kernel(const float* __restrict__ bvec)
{
    const int i   = blockIdx.x;
    const int tid = threadIdx.x;

    __shared__ float vals[DATTR];
    __shared__ float smax[4];
    __shared__ float sse[4];
    __shared__ float srs[4];

    for (int c = tid; c < DATTR; c += 128) {
        float v = bvec[c];
        #pragma unroll
        for (int s = 0; s < NSLICES; s++) v += g_partial[s][i][c];
        vals[c] = v;
    }
    __syncthreads();

    float m = -1e30f;
    for (int c = tid; c < DATTR; c += 128) m = fmaxf(m, vals[c]);
    #pragma unroll
    for (int o = 16; o; o >>= 1) m = fmaxf(m, __shfl_xor_sync(0xffffffffu, m, o));
    if ((tid & 31) == 0) smax[tid >> 5] = m;
    __syncthreads();
    m = fmaxf(fmaxf(smax[0], smax[1]), fmaxf(smax[2], smax[3]));

    float se = 0.f, rs = 0.f;
    for (int c = tid; c < DATTR; c += 128) {
        const float v = vals[c];
        se += expf(v - m);
        rs += v;
    }
    #pragma unroll
    for (int o = 16; o; o >>= 1) {
        se += __shfl_xor_sync(0xffffffffu, se, o);
        rs += __shfl_xor_sync(0xffffffffu, rs, o);
    }
    if ((tid & 31) == 0) { sse[tid >> 5] = se; srs[tid >> 5] = rs; }
    __syncthreads();

    if (tid == 0) {
        const float seT = sse[0] + sse[1] + sse[2] + sse[3];
        const float rsT = srs[0] + srs[1] + srs[2] + srs[3];
        const float lse = m + logf(seT);
        g_Sf[i] = rsT - (float)DATTR * lse;
    }
}

// ---------------------------------------------------------------------------
// Kernel 3: loss = mean over same-label upper pairs of (S_j - S_i)
// (label dtype sniff: int64 buffers have zero odd words since labels < 150)
// ---------------------------------------------------------------------------
__global__ __launch_bounds__(512) void pair_loss_kernel(
    const int* __restrict__ labw, float* __restrict__ out)
{
    __shared__ int           slab[B_SZ];
    __shared__ int           s_not64;
    __shared__ float         sS[B_SZ];
    __shared__ float         swsum[16];
    __shared__ unsigned int  swcnt[16];

    const int t = threadIdx.x;
    if (t == 0) s_not64 = 0;
    __syncthreads();

    if (t < 256 && labw[2 * t + 1] != 0) atomicOr(&s_not64, 1);
    __syncthreads();

    const bool is64 = (s_not64 == 0);
    slab[t] = is64 ? labw[2 * t] : labw[t];
    sS[t]   = g_Sf[t];
    __syncthreads();

    const int   li = slab[t];
    const float Si = sS[t];
    float        local = 0.f;
    unsigned int cnt   = 0;

    for (int j = t + 1; j < B_SZ; j++) {
        if (slab[j] == li) { local += sS[j] - Si; cnt++; }
    }

    #pragma unroll
    for (int o = 16; o; o >>= 1) {
        local += __shfl_xor_sync(0xffffffffu, local, o);
        cnt   += __shfl_xor_sync(0xffffffffu, cnt, o);
    }
    if ((t & 31) == 0) { swsum[t >> 5] = local; swcnt[t >> 5] = cnt; }
    __syncthreads();

    if (t == 0) {
        float s = 0.f; unsigned int c = 0;
        #pragma unroll
        for (int w = 0; w < 16; w++) { s += swsum[w]; c += swcnt[w]; }
        out[0] = (c > 0) ? (s / (float)c) : s;
    }
}

// ---------------------------------------------------------------------------
extern "C" void kernel_launch(void* const* d_in, const int* in_sizes, int n_in,
                              void* d_out, int out_size)
{
    const float* x   = (const float*)d_in[0];      // [512, 2048]
    const float* Wm  = (const float*)d_in[1];      // [2048, 312]
    const float* b   = (const float*)d_in[2];      // [312]
    // d_in[3] = seen_att : unused (cancels exactly for same-label pairs)
    const int*   lab = (const int*)d_in[4];        // [512] labels

    split_x_kernel<<<(B_SZ * DFEAT / 4) / 256, 256>>>(x);       // 1024 blocks
    split_w_kernel<<<dim3(10, 64), dim3(32, 8)>>>(Wm);
    mma_gemm_kernel<<<dim3(5, 4, 6), 256>>>();
    rowstats_kernel<<<B_SZ, 128>>>(b);
    pair_loss_kernel<<<1, B_SZ>>>(lab, (float*)d_out);
}